// round 13
// baseline (speedup 1.0000x reference)
#include <cuda_runtime.h>
#include <cuda_fp16.h>
#include <math.h>
#include <float.h>
#include <stdint.h>

#define SEQ 1024
#define DMODEL 4096
#define NH 32
#define HD 128
#define HB 102
#define RB 102

// ======================= static device scratch =======================
__device__ __align__(256) float g_Q[SEQ * DMODEL];
__device__ __align__(256) float g_K[SEQ * DMODEL];
__device__ __align__(256) float g_V[SEQ * DMODEL];
__device__ __align__(256) float g_P[(size_t)NH * SEQ * SEQ];
__device__ unsigned g_M[NH * SEQ * (SEQ / 32)];
__device__ __align__(256) __half g_Xhi[SEQ * DMODEL], g_Xlo[SEQ * DMODEL];
__device__ __align__(256) __half g_Whi[4][DMODEL * DMODEL];
__device__ __align__(256) __half g_Qhi[SEQ * DMODEL], g_Qlo[SEQ * DMODEL];
__device__ __align__(256) __half g_Khi[SEQ * DMODEL], g_Klo[SEQ * DMODEL];
__device__ __align__(256) __half g_AOhi[SEQ * DMODEL], g_AOlo[SEQ * DMODEL];

// ======================= helpers =======================
__device__ __forceinline__ uint32_t smem_u32(const void* p) {
    uint32_t a;
    asm("{ .reg .u64 t; cvta.to.shared.u64 t, %1; cvt.u32.u64 %0, t; }" : "=r"(a) : "l"(p));
    return a;
}
__device__ __forceinline__ void cp16(uint32_t dst, const void* src) {
    asm volatile("cp.async.cg.shared.global [%0], [%1], 16;" :: "r"(dst), "l"(src));
}
__device__ __forceinline__ void cp_commit() { asm volatile("cp.async.commit_group;" ::: "memory"); }
__device__ __forceinline__ void cp_wait1() { asm volatile("cp.async.wait_group 1;" ::: "memory"); }
__device__ __forceinline__ void cp_wait0() { asm volatile("cp.async.wait_group 0;" ::: "memory"); }

__device__ __forceinline__ void ldsm4(uint32_t* r, uint32_t addr) {
    asm volatile("ldmatrix.sync.aligned.m8n8.x4.shared.b16 {%0,%1,%2,%3}, [%4];"
        : "=r"(r[0]), "=r"(r[1]), "=r"(r[2]), "=r"(r[3]) : "r"(addr));
}
__device__ __forceinline__ void mma_fp16(float* c, const uint32_t* a, uint32_t b0, uint32_t b1) {
    asm volatile("mma.sync.aligned.m16n8k16.row.col.f32.f16.f16.f32 "
        "{%0,%1,%2,%3}, {%4,%5,%6,%7}, {%8,%9}, {%0,%1,%2,%3};"
        : "+f"(c[0]), "+f"(c[1]), "+f"(c[2]), "+f"(c[3])
        : "r"(a[0]), "r"(a[1]), "r"(a[2]), "r"(a[3]), "r"(b0), "r"(b1));
}

// ======================= 3-term GEMM core (QK logits, BN=64) =======================
#define A_SLAB 16384
#define B_SLAB 8192
#define STAGE (2 * A_SLAB + 2 * B_SLAB)
#define MM_SMEM (2 * STAGE)          /* 98304, shared by both GEMM variants */

__device__ __forceinline__ void ld_stage3(
    uint32_t st, const __half* Ahi, const __half* Alo,
    const __half* Bhi, const __half* Blo,
    int lda, int ldb, int k0, int tid)
{
#pragma unroll
    for (int it = 0; it < 4; it++) {
        int idx = it * 256 + tid;
        int row = idx >> 3, g = idx & 7;
        uint32_t off = row * 128 + ((g ^ (row & 7)) << 4);
        size_t s = (size_t)row * lda + k0 + g * 8;
        cp16(st + off, Ahi + s);
        cp16(st + A_SLAB + off, Alo + s);
    }
#pragma unroll
    for (int it = 0; it < 2; it++) {
        int idx = it * 256 + tid;
        int row = idx >> 3, g = idx & 7;
        uint32_t off = row * 128 + ((g ^ (row & 7)) << 4);
        size_t s = (size_t)row * ldb + k0 + g * 8;
        cp16(st + 2 * A_SLAB + off, Bhi + s);
        cp16(st + 2 * A_SLAB + B_SLAB + off, Blo + s);
    }
}

__device__ __forceinline__ void mm_hmma3(
    const __half* __restrict__ Ahi, const __half* __restrict__ Alo, int lda,
    const __half* __restrict__ Bhi, const __half* __restrict__ Blo, int ldb,
    float* __restrict__ C, int ldc, int nk, float scale)
{
    extern __shared__ char smem[];
    const uint32_t sb = smem_u32(smem);
    const int tid = threadIdx.x, lane = tid & 31, wid = tid >> 5;
    const int wm = wid & 3, wn = wid >> 2;

    float c[2][4][4];
#pragma unroll
    for (int i = 0; i < 2; i++)
#pragma unroll
        for (int j = 0; j < 4; j++)
#pragma unroll
            for (int q = 0; q < 4; q++) c[i][j][q] = 0.f;

    ld_stage3(sb, Ahi, Alo, Bhi, Blo, lda, ldb, 0, tid); cp_commit();
    ld_stage3(sb + STAGE, Ahi, Alo, Bhi, Blo, lda, ldb, 64, tid); cp_commit();

    const int axor = lane & 7;
    for (int ck = 0; ck < nk; ck++) {
        if (ck == nk - 1) cp_wait0(); else cp_wait1();
        __syncthreads();
        const uint32_t st = sb + (ck & 1) * STAGE;
#pragma unroll
        for (int k16 = 0; k16 < 4; k16++) {
            uint32_t ah[2][4], al[2][4], bh[2][4], bl[2][4];
#pragma unroll
            for (int i = 0; i < 2; i++) {
                int arow = wm * 32 + i * 16 + (lane & 15);
                uint32_t ad = st + (uint32_t)(arow * 128)
                            + (uint32_t)(((2 * k16 + (lane >> 4)) ^ axor) << 4);
                ldsm4(ah[i], ad);
                ldsm4(al[i], ad + A_SLAB);
            }
#pragma unroll
            for (int j4 = 0; j4 < 2; j4++) {
                int brow = wn * 32 + j4 * 16 + ((lane >> 4) << 3) + (lane & 7);
                uint32_t bd = st + 2 * A_SLAB + (uint32_t)(brow * 128)
                            + (uint32_t)(((2 * k16 + ((lane >> 3) & 1)) ^ axor) << 4);
                ldsm4(bh[j4], bd);
                ldsm4(bl[j4], bd + B_SLAB);
            }
#pragma unroll
            for (int i = 0; i < 2; i++)
#pragma unroll
                for (int j4 = 0; j4 < 2; j4++) {
                    mma_fp16(c[i][2 * j4],     ah[i], bh[j4][0], bh[j4][1]);
                    mma_fp16(c[i][2 * j4 + 1], ah[i], bh[j4][2], bh[j4][3]);
                }
#pragma unroll
            for (int i = 0; i < 2; i++)
#pragma unroll
                for (int j4 = 0; j4 < 2; j4++) {
                    mma_fp16(c[i][2 * j4],     al[i], bh[j4][0], bh[j4][1]);
                    mma_fp16(c[i][2 * j4 + 1], al[i], bh[j4][2], bh[j4][3]);
                }
#pragma unroll
            for (int i = 0; i < 2; i++)
#pragma unroll
                for (int j4 = 0; j4 < 2; j4++) {
                    mma_fp16(c[i][2 * j4],     ah[i], bl[j4][0], bl[j4][1]);
                    mma_fp16(c[i][2 * j4 + 1], ah[i], bl[j4][2], bl[j4][3]);
                }
        }
        __syncthreads();
        if (ck + 2 < nk) {
            ld_stage3(st, Ahi, Alo, Bhi, Blo, lda, ldb, (ck + 2) * 64, tid);
            cp_commit();
        }
    }

    const int r0 = wm * 32 + (lane >> 2);
    const int c0 = wn * 32 + (lane & 3) * 2;
#pragma unroll
    for (int i = 0; i < 2; i++)
#pragma unroll
        for (int j = 0; j < 4; j++) {
            float2 v0 = { c[i][j][0] * scale, c[i][j][1] * scale };
            float2 v1 = { c[i][j][2] * scale, c[i][j][3] * scale };
            *(float2*)&C[(size_t)(r0 + i * 16) * ldc + c0 + j * 8] = v0;
            *(float2*)&C[(size_t)(r0 + i * 16 + 8) * ldc + c0 + j * 8] = v1;
        }
}

// ======================= 2-term weight GEMM core (BN=128) =======================
// C[128 x 128] = Ahi*Bhi^T + Alo*Bhi^T.  No B residual -> slab freed, so
// BN doubles at the same 96KB/CTA: MMA:LDSM 4:1, B L2 traffic halved.
#define BW_SLAB 16384                 /* 128 rows x 128B */
#define STAGE_W (3 * BW_SLAB)         /* Ahi | Alo | Bhi = 49152 */

__device__ __forceinline__ void ld_stage_w(
    uint32_t st, const __half* Ahi, const __half* Alo,
    const __half* Bhi, int lda, int ldb, int k0, int tid)
{
#pragma unroll
    for (int it = 0; it < 4; it++) {
        int idx = it * 256 + tid;
        int row = idx >> 3, g = idx & 7;
        uint32_t off = row * 128 + ((g ^ (row & 7)) << 4);
        size_t sa = (size_t)row * lda + k0 + g * 8;
        size_t sbv = (size_t)row * ldb + k0 + g * 8;
        cp16(st + off, Ahi + sa);
        cp16(st + BW_SLAB + off, Alo + sa);
        cp16(st + 2 * BW_SLAB + off, Bhi + sbv);
    }
}

__device__ __forceinline__ void mm_hmma_w(
    const __half* __restrict__ Ahi, const __half* __restrict__ Alo, int lda,
    const __half* __restrict__ Bhi, int ldb,
    float* __restrict__ C, int ldc, int nk)
{
    extern __shared__ char smem[];
    const uint32_t sb = smem_u32(smem);
    const int tid = threadIdx.x, lane = tid & 31, wid = tid >> 5;
    const int wm = wid & 3, wn = wid >> 2;

    float c[2][8][4];
#pragma unroll
    for (int i = 0; i < 2; i++)
#pragma unroll
        for (int j = 0; j < 8; j++)
#pragma unroll
            for (int q = 0; q < 4; q++) c[i][j][q] = 0.f;

    ld_stage_w(sb, Ahi, Alo, Bhi, lda, ldb, 0, tid); cp_commit();
    ld_stage_w(sb + STAGE_W, Ahi, Alo, Bhi, lda, ldb, 64, tid); cp_commit();

    const int axor = lane & 7;
    for (int ck = 0; ck < nk; ck++) {
        if (ck == nk - 1) cp_wait0(); else cp_wait1();
        __syncthreads();
        const uint32_t st = sb + (ck & 1) * STAGE_W;
#pragma unroll
        for (int k16 = 0; k16 < 4; k16++) {
            uint32_t ah[2][4], al[2][4], bh[4][4];
#pragma unroll
            for (int i = 0; i < 2; i++) {
                int arow = wm * 32 + i * 16 + (lane & 15);
                uint32_t ad = st + (uint32_t)(arow * 128)
                            + (uint32_t)(((2 * k16 + (lane >> 4)) ^ axor) << 4);
                ldsm4(ah[i], ad);
                ldsm4(al[i], ad + BW_SLAB);
            }
#pragma unroll
            for (int j4 = 0; j4 < 4; j4++) {
                int brow = wn * 64 + j4 * 16 + ((lane >> 4) << 3) + (lane & 7);
                uint32_t bd = st + 2 * BW_SLAB + (uint32_t)(brow * 128)
                            + (uint32_t)(((2 * k16 + ((lane >> 3) & 1)) ^ axor) << 4);
                ldsm4(bh[j4], bd);
            }
            // term 1: Ahi * Bhi (8 distinct accumulators per i)
#pragma unroll
            for (int i = 0; i < 2; i++)
#pragma unroll
                for (int j4 = 0; j4 < 4; j4++) {
                    mma_fp16(c[i][2 * j4],     ah[i], bh[j4][0], bh[j4][1]);
                    mma_fp16(c[i][2 * j4 + 1], ah[i], bh[j4][2], bh[j4][3]);
                }
            // term 2: Alo * Bhi
#pragma unroll
            for (int i = 0; i < 2; i++)
#pragma unroll
                for (int j4 = 0; j4 < 4; j4++) {
                    mma_fp16(c[i][2 * j4],     al[i], bh[j4][0], bh[j4][1]);
                    mma_fp16(c[i][2 * j4 + 1], al[i], bh[j4][2], bh[j4][3]);
                }
        }
        __syncthreads();
        if (ck + 2 < nk) {
            ld_stage_w(st, Ahi, Alo, Bhi, lda, ldb, (ck + 2) * 64, tid);
            cp_commit();
        }
    }

    const int r0 = wm * 32 + (lane >> 2);
    const int c0 = wn * 64 + (lane & 3) * 2;
#pragma unroll
    for (int i = 0; i < 2; i++)
#pragma unroll
        for (int j = 0; j < 8; j++) {
            float2 v0 = { c[i][j][0], c[i][j][1] };
            float2 v1 = { c[i][j][2], c[i][j][3] };
            *(float2*)&C[(size_t)(r0 + i * 16) * ldc + c0 + j * 8] = v0;
            *(float2*)&C[(size_t)(r0 + i * 16 + 8) * ldc + c0 + j * 8] = v1;
        }
}

// ======================= conversion fp32 -> fp16 (hi, optional lo) =======================
#define X4 (SEQ * DMODEL / 4)
#define W4 (DMODEL * DMODEL / 4)

__device__ __forceinline__ void cvt_one(const float* src, __half* hi, __half* lo,
                                        long long r, bool write_lo)
{
    float4 v = ((const float4*)src)[r];
    __half h0 = __float2half(v.x), h1 = __float2half(v.y);
    __half h2 = __float2half(v.z), h3 = __float2half(v.w);
    __half2 H01; H01.x = h0; H01.y = h1;
    __half2 H23; H23.x = h2; H23.y = h3;
    *(__half2*)(hi + 4 * (size_t)r)     = H01;
    *(__half2*)(hi + 4 * (size_t)r + 2) = H23;
    if (write_lo) {
        __half2 L01, L23;
        L01.x = __float2half(v.x - __half2float(h0));
        L01.y = __float2half(v.y - __half2float(h1));
        L23.x = __float2half(v.z - __half2float(h2));
        L23.y = __float2half(v.w - __half2float(h3));
        *(__half2*)(lo + 4 * (size_t)r)     = L01;
        *(__half2*)(lo + 4 * (size_t)r + 2) = L23;
    }
}

__global__ __launch_bounds__(256) void cvt_main_kernel(
    const float* __restrict__ X, const float* __restrict__ Wq,
    const float* __restrict__ Wk)
{
    long long i = (long long)blockIdx.x * 256 + threadIdx.x;
    if (i < X4)                        cvt_one(X,  g_Xhi,    g_Xlo, i, true);
    else if ((i -= X4) < W4)           cvt_one(Wq, g_Whi[0], 0, i, false);
    else if ((i -= W4) < W4)           cvt_one(Wk, g_Whi[1], 0, i, false);
}

__global__ __launch_bounds__(256) void cvt_aux_kernel(
    const float* __restrict__ Wv, const float* __restrict__ Wo)
{
    long long i = (long long)blockIdx.x * 256 + threadIdx.x;
    if (i < W4)                        cvt_one(Wv, g_Whi[2], 0, i, false);
    else if ((i -= W4) < W4)           cvt_one(Wo, g_Whi[3], 0, i, false);
}

// ======================= GEMM wrappers =======================
__global__ __launch_bounds__(256, 2) void mm_qkproj_kernel()
{
    const int z = blockIdx.z;
    const int m0 = blockIdx.y * 128, n0 = blockIdx.x * 128;
    float* O = (z == 0) ? g_Q : g_K;
    mm_hmma_w(g_Xhi + (size_t)m0 * DMODEL, g_Xlo + (size_t)m0 * DMODEL, DMODEL,
              g_Whi[z] + (size_t)n0 * DMODEL, DMODEL,
              O + (size_t)m0 * DMODEL + n0, DMODEL, DMODEL / 64);
}

__global__ __launch_bounds__(256, 2) void mm_v_kernel()
{
    const int m0 = blockIdx.y * 128, n0 = blockIdx.x * 128;
    mm_hmma_w(g_Xhi + (size_t)m0 * DMODEL, g_Xlo + (size_t)m0 * DMODEL, DMODEL,
              g_Whi[2] + (size_t)n0 * DMODEL, DMODEL,
              g_V + (size_t)m0 * DMODEL + n0, DMODEL, DMODEL / 64);
}

__global__ __launch_bounds__(256, 2) void mm_o_kernel(float* __restrict__ out, int yofs)
{
    const int m0 = (blockIdx.y + yofs) * 128, n0 = blockIdx.x * 128;
    mm_hmma_w(g_AOhi + (size_t)m0 * DMODEL, g_AOlo + (size_t)m0 * DMODEL, DMODEL,
              g_Whi[3] + (size_t)n0 * DMODEL, DMODEL,
              out + (size_t)m0 * DMODEL + n0, DMODEL, DMODEL / 64);
}

__global__ __launch_bounds__(256, 2) void mm_qk_kernel(int hofs)
{
    const int h = blockIdx.z + hofs;
    const int m0 = blockIdx.y * 128, n0 = blockIdx.x * 64;
    if (n0 > m0 + 127) return;
    mm_hmma3(g_Qhi + (size_t)m0 * DMODEL + h * HD, g_Qlo + (size_t)m0 * DMODEL + h * HD, DMODEL,
             g_Khi + (size_t)n0 * DMODEL + h * HD, g_Klo + (size_t)n0 * DMODEL + h * HD, DMODEL,
             g_P + (size_t)h * SEQ * SEQ + (size_t)m0 * SEQ + n0, SEQ,
             HD / 64, 0.08838834764831845f);
}

// ======================= RoPE =======================
__global__ void rope_kernel()
{
    int idx = blockIdx.x * blockDim.x + threadIdx.x;
    const float* src = blockIdx.y ? g_K : g_Q;
    __half* hi = blockIdx.y ? g_Khi : g_Qhi;
    __half* lo = blockIdx.y ? g_Klo : g_Qlo;
    int p = idx & 63;
    int h = (idx >> 6) & 31;
    int s = idx >> 11;
    float inv = 1.0f / powf(10000.0f, (float)(2 * p) * (1.0f / 128.0f));
    float ang = (float)s * inv;
    float sn, c;
    sincosf(ang, &sn, &c);
    size_t b = (size_t)s * DMODEL + h * HD + p;
    float q0 = src[b], q1 = src[b + 64];
    float r0 = q0 * c - q1 * sn;
    float r1 = q1 * c + q0 * sn;
    __half h0 = __float2half(r0);
    __half h1 = __float2half(r1);
    hi[b] = h0;      lo[b]      = __float2half(r0 - __half2float(h0));
    hi[b + 64] = h1; lo[b + 64] = __float2half(r1 - __half2float(h1));
}

// ======================= softmax (per head-group) =======================
__global__ __launch_bounds__(256) void softmax_kernel(int hofs)
{
    const int i = blockIdx.x, h = blockIdx.y + hofs;
    float* row = g_P + (size_t)h * SEQ * SEQ + (size_t)i * SEQ;
    const int n = i + 1;
    const int tid = threadIdx.x;
    const int lane = tid & 31, wid = tid >> 5;
    __shared__ float red[16];

    float m = -FLT_MAX;
    for (int j = tid; j < n; j += 256) m = fmaxf(m, row[j]);
#pragma unroll
    for (int o = 16; o; o >>= 1) m = fmaxf(m, __shfl_xor_sync(0xffffffffu, m, o));
    if (lane == 0) red[wid] = m;
    __syncthreads();
    m = red[0];
#pragma unroll
    for (int w = 1; w < 8; w++) m = fmaxf(m, red[w]);

    float s = 0.f;
    for (int j = tid; j < n; j += 256) s += expf(row[j] - m);
#pragma unroll
    for (int o = 16; o; o >>= 1) s += __shfl_xor_sync(0xffffffffu, s, o);
    if (lane == 0) red[8 + wid] = s;
    __syncthreads();
    float tot = 0.f;
#pragma unroll
    for (int w = 0; w < 8; w++) tot += red[8 + w];
    const float invs = 1.0f / tot;

    for (int j = tid; j < SEQ; j += 256)
        row[j] = (j < n) ? expf(row[j] - m) * invs : 0.f;
}

// ======================= H2O sequential scan (per head-group) =======================
__global__ __launch_bounds__(128) void scan_kernel(int hofs)
{
    const int h = blockIdx.x + hofs;
    const int tid = threadIdx.x;
    const int lane = tid & 31, wid = tid >> 5;
    __shared__ float rowbuf[2][SEQ];
    __shared__ int   lst[128];
    __shared__ float skey[128];
    __shared__ unsigned mw[32];
    __shared__ unsigned skipm;
    const float* P = g_P + (size_t)h * SEQ * SEQ;
    unsigned* MB = g_M + h * SEQ * (SEQ / 32);

    if (tid < HB) {
        float s = 0.f;
        for (int i = 0; i < HB; i++) s += P[(size_t)i * SEQ + tid];
        skey[tid] = s;
        lst[tid] = tid;
    }
    {
        uint32_t dst = smem_u32(&rowbuf[HB & 1][0]);
        const float* src = P + (size_t)HB * SEQ;
        for (int g = tid; g < SEQ / 4; g += 128) cp16(dst + g * 16, src + g * 4);
        cp_commit();
    }
    cp_wait0();
    __syncthreads();

    int cnt = HB;
    for (int t = HB; t < SEQ; t++) {
        if (t + 1 < SEQ) {
            uint32_t dst = smem_u32(&rowbuf[(t + 1) & 1][0]);
            const float* src = P + (size_t)(t + 1) * SEQ;
            for (int g = tid; g < SEQ / 4; g += 128) cp16(dst + g * 16, src + g * 4);
            cp_commit();
        }
        if (wid == 0) {
            const float* Prow = rowbuf[t & 1];
            if (lane == 0) skipm = 0u;
            __syncwarp();

            const int r = cnt - (HB - 1);
            for (int rep = 0; rep < r; rep++) {
                const unsigned sk = skipm;
                float bv = FLT_MAX; int bidx = -1; int bpos = 0;
                for (int p = lane; p < cnt; p += 32) {
                    int ix = lst[p];
                    if (ix < 4 && ((sk >> ix) & 1u)) continue;
                    float v = skey[p];
                    if (v < bv || (v == bv && ix > bidx)) { bv = v; bidx = ix; bpos = p; }
                }
#pragma unroll
                for (int o = 16; o; o >>= 1) {
                    float ov = __shfl_down_sync(0xffffffffu, bv, o);
                    int   oi = __shfl_down_sync(0xffffffffu, bidx, o);
                    int   op = __shfl_down_sync(0xffffffffu, bpos, o);
                    if (ov < bv || (ov == bv && oi > bidx)) { bv = ov; bidx = oi; bpos = op; }
                }
                bidx = __shfl_sync(0xffffffffu, bidx, 0);
                bpos = __shfl_sync(0xffffffffu, bpos, 0);
                if (bidx >= 4) {
                    if (lane == 0) {
                        lst[bpos]  = lst[cnt - 1];
                        skey[bpos] = skey[cnt - 1];
                    }
                    cnt--;
                } else {
                    if (lane == 0) skipm |= (1u << bidx);
                }
                __syncwarp();
            }
            if (lane == 0) { lst[cnt] = t; skey[cnt] = 0.f; }
            cnt++;
            mw[lane] = 0u;
            __syncwarp();
            for (int p = lane; p < cnt; p += 32) {
                int ix = lst[p];
                skey[p] += Prow[ix];
                atomicOr(&mw[ix >> 5], 1u << (ix & 31));
            }
            __syncwarp();
            MB[t * 32 + lane] = mw[lane];
        }
        cp_wait0();
        __syncthreads();
    }
}

// ======================= masked renorm softmax + P@V (row-half) =======================
__global__ __launch_bounds__(128) void pv_kernel(int bofs)
{
    const int h = blockIdx.y;
    const int tid = threadIdx.x;
    const int lane = tid & 31, wid = tid >> 5;
    __shared__ float pv[224];
    __shared__ int   pj[224];
    __shared__ int   wbase[4];
    __shared__ float wsum[4];
    __shared__ int   s_cnt;
    __shared__ float s_sum;

    for (int u8 = 0; u8 < 8; u8++) {
        const int s = (blockIdx.x + bofs) * 8 + u8;
        const float* Prow = g_P + (size_t)h * SEQ * SEQ + (size_t)s * SEQ;
        const unsigned* mb = g_M + (h * SEQ + s) * (SEQ / 32);

        float pr[8]; bool al[8];
        int c = 0; float lsum = 0.f;
        const int j0 = tid * 8;
#pragma unroll
        for (int u = 0; u < 8; u++) {
            const int j = j0 + u;
            bool a;
            if (s < HB) a = (j <= s);
            else        a = (j <= s) && ((j + RB >= s) || ((mb[j >> 5] >> (j & 31)) & 1u));
            float val = a ? Prow[j] : 0.f;
            al[u] = a; pr[u] = val;
            if (a) { c++; lsum += val; }
        }
        int inc = c;
#pragma unroll
        for (int o = 1; o < 32; o <<= 1) {
            int v = __shfl_up_sync(0xffffffffu, inc, o);
            if (lane >= o) inc += v;
        }
        float ws = lsum;
#pragma unroll
        for (int o = 16; o; o >>= 1) ws += __shfl_xor_sync(0xffffffffu, ws, o);
        if (lane == 31) wbase[wid] = inc;
        if (lane == 0)  wsum[wid] = ws;
        __syncthreads();
        if (tid == 0) {
            int tot = 0;
#pragma unroll
            for (int w = 0; w < 4; w++) { int b = wbase[w]; wbase[w] = tot; tot += b; }
            s_cnt = tot;
            s_sum = wsum[0] + wsum[1] + wsum[2] + wsum[3];
        }
        __syncthreads();
        int k = wbase[wid] + inc - c;
#pragma unroll
        for (int u = 0; u < 8; u++)
            if (al[u]) { pv[k] = pr[u]; pj[k] = j0 + u; k++; }
        __syncthreads();

        const int cnt = s_cnt;
        const float inv = 1.0f / s_sum;
        const float* Vh = g_V + h * HD + tid;
        float acc = 0.f;
        int m2 = 0;
        for (; m2 + 4 <= cnt; m2 += 4) {
            acc += pv[m2 + 0] * Vh[(size_t)pj[m2 + 0] * DMODEL];
            acc += pv[m2 + 1] * Vh[(size_t)pj[m2 + 1] * DMODEL];
            acc += pv[m2 + 2] * Vh[(size_t)pj[m2 + 2] * DMODEL];
            acc += pv[m2 + 3] * Vh[(size_t)pj[m2 + 3] * DMODEL];
        }
        for (; m2 < cnt; m2++) acc += pv[m2] * Vh[(size_t)pj[m2] * DMODEL];

        float v = acc * inv;
        __half hv = __float2half(v);
        size_t oi = (size_t)s * DMODEL + h * HD + tid;
        g_AOhi[oi] = hv;
        g_AOlo[oi] = __float2half(v - __half2float(hv));
        __syncthreads();
    }
}

// ======================= launch (deep fork-join inside capture) =======================
extern "C" void kernel_launch(void* const* d_in, const int* in_sizes, int n_in,
                              void* d_out, int out_size)
{
    const float* X  = (const float*)d_in[0];
    const float* Wq = (const float*)d_in[2];
    const float* Wk = (const float*)d_in[3];
    const float* Wv = (const float*)d_in[4];
    const float* Wo = (const float*)d_in[5];
    float* out = (float*)d_out;

    static cudaStream_t s_aux = 0, s2 = 0;
    static cudaEvent_t ev_begin = 0, ev_xcvt = 0, ev_vdone = 0,
                       ev_rope = 0, ev_g0 = 0, ev_g1 = 0, ev_pvb = 0;
    if (!s_aux) {
        int lo_p, hi_p;
        cudaDeviceGetStreamPriorityRange(&lo_p, &hi_p);
        cudaStreamCreateWithPriority(&s_aux, cudaStreamNonBlocking, lo_p);
        cudaStreamCreateWithFlags(&s2, cudaStreamNonBlocking);
        cudaEventCreateWithFlags(&ev_begin, cudaEventDisableTiming);
        cudaEventCreateWithFlags(&ev_xcvt,  cudaEventDisableTiming);
        cudaEventCreateWithFlags(&ev_vdone, cudaEventDisableTiming);
        cudaEventCreateWithFlags(&ev_rope,  cudaEventDisableTiming);
        cudaEventCreateWithFlags(&ev_g0,    cudaEventDisableTiming);
        cudaEventCreateWithFlags(&ev_g1,    cudaEventDisableTiming);
        cudaEventCreateWithFlags(&ev_pvb,   cudaEventDisableTiming);
    }

    cudaFuncSetAttribute(mm_qkproj_kernel, cudaFuncAttributeMaxDynamicSharedMemorySize, MM_SMEM);
    cudaFuncSetAttribute(mm_v_kernel,      cudaFuncAttributeMaxDynamicSharedMemorySize, MM_SMEM);
    cudaFuncSetAttribute(mm_qk_kernel,     cudaFuncAttributeMaxDynamicSharedMemorySize, MM_SMEM);
    cudaFuncSetAttribute(mm_o_kernel,      cudaFuncAttributeMaxDynamicSharedMemorySize, MM_SMEM);

    // fork
    cudaEventRecord(ev_begin, 0);
    cudaStreamWaitEvent(s_aux, ev_begin, 0);
    cudaStreamWaitEvent(s2, ev_begin, 0);

    // aux: deferred weight conversions + V projection
    cvt_aux_kernel<<<(2 * W4 + 255) / 256, 256, 0, s_aux>>>(Wv, Wo);

    // main: X/Wq/Wk conversion, Q/K projections, rope
    cvt_main_kernel<<<(X4 + 2 * W4 + 255) / 256, 256>>>(X, Wq, Wk);
    cudaEventRecord(ev_xcvt, 0);

    mm_qkproj_kernel<<<dim3(DMODEL / 128, SEQ / 128, 2), 256, MM_SMEM>>>();
    rope_kernel<<<dim3((SEQ * NH * 64) / 256, 2), 256>>>();
    cudaEventRecord(ev_rope, 0);

    // aux: V projection once X is converted
    cudaStreamWaitEvent(s_aux, ev_xcvt, 0);
    mm_v_kernel<<<dim3(DMODEL / 128, SEQ / 128), 256, MM_SMEM, s_aux>>>();
    cudaEventRecord(ev_vdone, s_aux);

    // head-group 0 on default: qk -> softmax -> scan
    mm_qk_kernel<<<dim3(SEQ / 64, SEQ / 128, NH / 2), 256, MM_SMEM>>>(0);
    softmax_kernel<<<dim3(SEQ, NH / 2), 256>>>(0);
    scan_kernel<<<NH / 2, 128>>>(0);
    cudaEventRecord(ev_g0, 0);

    // head-group 1 on s2
    cudaStreamWaitEvent(s2, ev_rope, 0);
    mm_qk_kernel<<<dim3(SEQ / 64, SEQ / 128, NH / 2), 256, MM_SMEM, s2>>>(NH / 2);
    softmax_kernel<<<dim3(SEQ, NH / 2), 256, 0, s2>>>(NH / 2);
    scan_kernel<<<NH / 2, 128, 0, s2>>>(NH / 2);
    cudaEventRecord(ev_g1, s2);

    // pv halves
    cudaStreamWaitEvent(0, ev_g1, 0);
    cudaStreamWaitEvent(0, ev_vdone, 0);
    cudaStreamWaitEvent(s2, ev_g0, 0);
    cudaStreamWaitEvent(s2, ev_vdone, 0);

    pv_kernel<<<dim3(SEQ / 16, NH), 128>>>(0);
    pv_kernel<<<dim3(SEQ / 16, NH), 128, 0, s2>>>(SEQ / 16);
    cudaEventRecord(ev_pvb, s2);

    // mm_o halves: first half overlaps second pv half
    mm_o_kernel<<<dim3(DMODEL / 128, SEQ / 256), 256, MM_SMEM>>>(out, 0);
    cudaStreamWaitEvent(0, ev_pvb, 0);
    mm_o_kernel<<<dim3(DMODEL / 128, SEQ / 256), 256, MM_SMEM>>>(out, SEQ / 256);
}

// round 14
// speedup vs baseline: 1.0163x; 1.0163x over previous
#include <cuda_runtime.h>
#include <cuda_fp16.h>
#include <math.h>
#include <float.h>
#include <stdint.h>

#define SEQ 1024
#define DMODEL 4096
#define NH 32
#define HD 128
#define HB 102
#define RB 102

// ======================= static device scratch =======================
__device__ __align__(256) float g_Q[SEQ * DMODEL];
__device__ __align__(256) float g_K[SEQ * DMODEL];
__device__ __align__(256) float g_V[SEQ * DMODEL];
__device__ __align__(256) float g_P[(size_t)NH * SEQ * SEQ];
__device__ unsigned g_M[NH * SEQ * (SEQ / 32)];
__device__ __align__(256) __half g_Xhi[SEQ * DMODEL], g_Xlo[SEQ * DMODEL];
__device__ __align__(256) __half g_Whi[4][DMODEL * DMODEL];
__device__ __align__(256) __half g_Qhi[SEQ * DMODEL], g_Qlo[SEQ * DMODEL];
__device__ __align__(256) __half g_Khi[SEQ * DMODEL], g_Klo[SEQ * DMODEL];
__device__ __align__(256) __half g_AOhi[SEQ * DMODEL], g_AOlo[SEQ * DMODEL];

// ======================= helpers =======================
__device__ __forceinline__ uint32_t smem_u32(const void* p) {
    uint32_t a;
    asm("{ .reg .u64 t; cvta.to.shared.u64 t, %1; cvt.u32.u64 %0, t; }" : "=r"(a) : "l"(p));
    return a;
}
__device__ __forceinline__ void cp16(uint32_t dst, const void* src) {
    asm volatile("cp.async.cg.shared.global [%0], [%1], 16;" :: "r"(dst), "l"(src));
}
__device__ __forceinline__ void cp_commit() { asm volatile("cp.async.commit_group;" ::: "memory"); }
__device__ __forceinline__ void cp_wait1() { asm volatile("cp.async.wait_group 1;" ::: "memory"); }
__device__ __forceinline__ void cp_wait0() { asm volatile("cp.async.wait_group 0;" ::: "memory"); }

__device__ __forceinline__ void ldsm4(uint32_t* r, uint32_t addr) {
    asm volatile("ldmatrix.sync.aligned.m8n8.x4.shared.b16 {%0,%1,%2,%3}, [%4];"
        : "=r"(r[0]), "=r"(r[1]), "=r"(r[2]), "=r"(r[3]) : "r"(addr));
}
__device__ __forceinline__ void mma_fp16(float* c, const uint32_t* a, uint32_t b0, uint32_t b1) {
    asm volatile("mma.sync.aligned.m16n8k16.row.col.f32.f16.f16.f32 "
        "{%0,%1,%2,%3}, {%4,%5,%6,%7}, {%8,%9}, {%0,%1,%2,%3};"
        : "+f"(c[0]), "+f"(c[1]), "+f"(c[2]), "+f"(c[3])
        : "r"(a[0]), "r"(a[1]), "r"(a[2]), "r"(a[3]), "r"(b0), "r"(b1));
}

// ======================= split-fp16 HMMA GEMM core (R12 config, BN=64) =======================
#define A_SLAB 16384
#define B_SLAB 8192
#define STAGE (2 * A_SLAB + 2 * B_SLAB)
#define MM_SMEM (2 * STAGE)

__device__ __forceinline__ void ld_stage(
    uint32_t st, const __half* Ahi, const __half* Alo,
    const __half* Bhi, const __half* Blo,
    int lda, int ldb, int k0, int tid, int terms)
{
#pragma unroll
    for (int it = 0; it < 4; it++) {
        int idx = it * 256 + tid;
        int row = idx >> 3, g = idx & 7;
        uint32_t off = row * 128 + ((g ^ (row & 7)) << 4);
        size_t s = (size_t)row * lda + k0 + g * 8;
        cp16(st + off, Ahi + s);
        cp16(st + A_SLAB + off, Alo + s);
    }
#pragma unroll
    for (int it = 0; it < 2; it++) {
        int idx = it * 256 + tid;
        int row = idx >> 3, g = idx & 7;
        uint32_t off = row * 128 + ((g ^ (row & 7)) << 4);
        size_t s = (size_t)row * ldb + k0 + g * 8;
        cp16(st + 2 * A_SLAB + off, Bhi + s);
        if (terms == 3)
            cp16(st + 2 * A_SLAB + B_SLAB + off, Blo + s);
    }
}

__device__ __forceinline__ void mm_hmma(
    const __half* __restrict__ Ahi, const __half* __restrict__ Alo, int lda,
    const __half* __restrict__ Bhi, const __half* __restrict__ Blo, int ldb,
    float* __restrict__ C, int ldc, int nk, float scale, int terms)
{
    extern __shared__ char smem[];
    const uint32_t sb = smem_u32(smem);
    const int tid = threadIdx.x, lane = tid & 31, wid = tid >> 5;
    const int wm = wid & 3, wn = wid >> 2;

    float c[2][4][4];
#pragma unroll
    for (int i = 0; i < 2; i++)
#pragma unroll
        for (int j = 0; j < 4; j++)
#pragma unroll
            for (int q = 0; q < 4; q++) c[i][j][q] = 0.f;

    ld_stage(sb, Ahi, Alo, Bhi, Blo, lda, ldb, 0, tid, terms); cp_commit();
    ld_stage(sb + STAGE, Ahi, Alo, Bhi, Blo, lda, ldb, 64, tid, terms); cp_commit();

    const int axor = lane & 7;
    for (int ck = 0; ck < nk; ck++) {
        if (ck == nk - 1) cp_wait0(); else cp_wait1();
        __syncthreads();
        const uint32_t st = sb + (ck & 1) * STAGE;
#pragma unroll
        for (int k16 = 0; k16 < 4; k16++) {
            uint32_t ah[2][4], al[2][4], bh[2][4], bl[2][4];
#pragma unroll
            for (int i = 0; i < 2; i++) {
                int arow = wm * 32 + i * 16 + (lane & 15);
                uint32_t ad = st + (uint32_t)(arow * 128)
                            + (uint32_t)(((2 * k16 + (lane >> 4)) ^ axor) << 4);
                ldsm4(ah[i], ad);
                ldsm4(al[i], ad + A_SLAB);
            }
#pragma unroll
            for (int j4 = 0; j4 < 2; j4++) {
                int brow = wn * 32 + j4 * 16 + ((lane >> 4) << 3) + (lane & 7);
                uint32_t bd = st + 2 * A_SLAB + (uint32_t)(brow * 128)
                            + (uint32_t)(((2 * k16 + ((lane >> 3) & 1)) ^ axor) << 4);
                ldsm4(bh[j4], bd);
                if (terms == 3) ldsm4(bl[j4], bd + B_SLAB);
            }
#pragma unroll
            for (int i = 0; i < 2; i++)
#pragma unroll
                for (int j4 = 0; j4 < 2; j4++) {
                    mma_fp16(c[i][2 * j4],     ah[i], bh[j4][0], bh[j4][1]);
                    mma_fp16(c[i][2 * j4 + 1], ah[i], bh[j4][2], bh[j4][3]);
                }
#pragma unroll
            for (int i = 0; i < 2; i++)
#pragma unroll
                for (int j4 = 0; j4 < 2; j4++) {
                    mma_fp16(c[i][2 * j4],     al[i], bh[j4][0], bh[j4][1]);
                    mma_fp16(c[i][2 * j4 + 1], al[i], bh[j4][2], bh[j4][3]);
                }
            if (terms == 3) {
#pragma unroll
                for (int i = 0; i < 2; i++)
#pragma unroll
                    for (int j4 = 0; j4 < 2; j4++) {
                        mma_fp16(c[i][2 * j4],     ah[i], bl[j4][0], bl[j4][1]);
                        mma_fp16(c[i][2 * j4 + 1], ah[i], bl[j4][2], bl[j4][3]);
                    }
            }
        }
        __syncthreads();
        if (ck + 2 < nk) {
            ld_stage(st, Ahi, Alo, Bhi, Blo, lda, ldb, (ck + 2) * 64, tid, terms);
            cp_commit();
        }
    }

    const int r0 = wm * 32 + (lane >> 2);
    const int c0 = wn * 32 + (lane & 3) * 2;
#pragma unroll
    for (int i = 0; i < 2; i++)
#pragma unroll
        for (int j = 0; j < 4; j++) {
            float2 v0 = { c[i][j][0] * scale, c[i][j][1] * scale };
            float2 v1 = { c[i][j][2] * scale, c[i][j][3] * scale };
            *(float2*)&C[(size_t)(r0 + i * 16) * ldc + c0 + j * 8] = v0;
            *(float2*)&C[(size_t)(r0 + i * 16 + 8) * ldc + c0 + j * 8] = v1;
        }
}

// ======================= conversion fp32 -> fp16 (hi, optional lo) =======================
#define X4 (SEQ * DMODEL / 4)
#define W4 (DMODEL * DMODEL / 4)

__device__ __forceinline__ void cvt_one(const float* src, __half* hi, __half* lo,
                                        long long r, bool write_lo)
{
    float4 v = ((const float4*)src)[r];
    __half h0 = __float2half(v.x), h1 = __float2half(v.y);
    __half h2 = __float2half(v.z), h3 = __float2half(v.w);
    __half2 H01; H01.x = h0; H01.y = h1;
    __half2 H23; H23.x = h2; H23.y = h3;
    *(__half2*)(hi + 4 * (size_t)r)     = H01;
    *(__half2*)(hi + 4 * (size_t)r + 2) = H23;
    if (write_lo) {
        __half2 L01, L23;
        L01.x = __float2half(v.x - __half2float(h0));
        L01.y = __float2half(v.y - __half2float(h1));
        L23.x = __float2half(v.z - __half2float(h2));
        L23.y = __float2half(v.w - __half2float(h3));
        *(__half2*)(lo + 4 * (size_t)r)     = L01;
        *(__half2*)(lo + 4 * (size_t)r + 2) = L23;
    }
}

__global__ __launch_bounds__(256) void cvt_main_kernel(
    const float* __restrict__ X, const float* __restrict__ Wq,
    const float* __restrict__ Wk)
{
    long long i = (long long)blockIdx.x * 256 + threadIdx.x;
    if (i < X4)                        cvt_one(X,  g_Xhi,    g_Xlo, i, true);
    else if ((i -= X4) < W4)           cvt_one(Wq, g_Whi[0], 0, i, false);
    else if ((i -= W4) < W4)           cvt_one(Wk, g_Whi[1], 0, i, false);
}

__global__ __launch_bounds__(256) void cvt_aux_kernel(
    const float* __restrict__ Wv, const float* __restrict__ Wo)
{
    long long i = (long long)blockIdx.x * 256 + threadIdx.x;
    if (i < W4)                        cvt_one(Wv, g_Whi[2], 0, i, false);
    else if ((i -= W4) < W4)           cvt_one(Wo, g_Whi[3], 0, i, false);
}

// ======================= GEMM wrappers =======================
__global__ __launch_bounds__(256, 2) void mm_qkproj_kernel()
{
    const int z = blockIdx.z;
    const int m0 = blockIdx.y * 128, n0 = blockIdx.x * 64;
    float* O = (z == 0) ? g_Q : g_K;
    mm_hmma(g_Xhi + (size_t)m0 * DMODEL, g_Xlo + (size_t)m0 * DMODEL, DMODEL,
            g_Whi[z] + (size_t)n0 * DMODEL, 0, DMODEL,
            O + (size_t)m0 * DMODEL + n0, DMODEL, DMODEL / 64, 1.0f, 2);
}

__global__ __launch_bounds__(256, 2) void mm_v_kernel()
{
    const int m0 = blockIdx.y * 128, n0 = blockIdx.x * 64;
    mm_hmma(g_Xhi + (size_t)m0 * DMODEL, g_Xlo + (size_t)m0 * DMODEL, DMODEL,
            g_Whi[2] + (size_t)n0 * DMODEL, 0, DMODEL,
            g_V + (size_t)m0 * DMODEL + n0, DMODEL, DMODEL / 64, 1.0f, 2);
}

__global__ __launch_bounds__(256, 2) void mm_o_kernel(float* __restrict__ out, int yofs)
{
    const int m0 = (blockIdx.y + yofs) * 128, n0 = blockIdx.x * 64;
    mm_hmma(g_AOhi + (size_t)m0 * DMODEL, g_AOlo + (size_t)m0 * DMODEL, DMODEL,
            g_Whi[3] + (size_t)n0 * DMODEL, 0, DMODEL,
            out + (size_t)m0 * DMODEL + n0, DMODEL, DMODEL / 64, 1.0f, 2);
}

__global__ __launch_bounds__(256, 2) void mm_qk_kernel(int hofs)
{
    const int h = blockIdx.z + hofs;
    const int m0 = blockIdx.y * 128, n0 = blockIdx.x * 64;
    if (n0 > m0 + 127) return;
    mm_hmma(g_Qhi + (size_t)m0 * DMODEL + h * HD, g_Qlo + (size_t)m0 * DMODEL + h * HD, DMODEL,
            g_Khi + (size_t)n0 * DMODEL + h * HD, g_Klo + (size_t)n0 * DMODEL + h * HD, DMODEL,
            g_P + (size_t)h * SEQ * SEQ + (size_t)m0 * SEQ + n0, SEQ,
            HD / 64, 0.08838834764831845f, 3);
}

// ======================= RoPE =======================
__global__ void rope_kernel()
{
    int idx = blockIdx.x * blockDim.x + threadIdx.x;
    const float* src = blockIdx.y ? g_K : g_Q;
    __half* hi = blockIdx.y ? g_Khi : g_Qhi;
    __half* lo = blockIdx.y ? g_Klo : g_Qlo;
    int p = idx & 63;
    int h = (idx >> 6) & 31;
    int s = idx >> 11;
    float inv = 1.0f / powf(10000.0f, (float)(2 * p) * (1.0f / 128.0f));
    float ang = (float)s * inv;
    float sn, c;
    sincosf(ang, &sn, &c);
    size_t b = (size_t)s * DMODEL + h * HD + p;
    float q0 = src[b], q1 = src[b + 64];
    float r0 = q0 * c - q1 * sn;
    float r1 = q1 * c + q0 * sn;
    __half h0 = __float2half(r0);
    __half h1 = __float2half(r1);
    hi[b] = h0;      lo[b]      = __float2half(r0 - __half2float(h0));
    hi[b + 64] = h1; lo[b + 64] = __float2half(r1 - __half2float(h1));
}

// ======================= softmax (per head-group) =======================
// Writes only j <= i (probs). Above-diagonal region of g_P left unwritten —
// all downstream readers (scan triangular acc0, masked gathers, masked pv)
// only touch j <= row.
__global__ __launch_bounds__(256) void softmax_kernel(int hofs)
{
    const int i = blockIdx.x, h = blockIdx.y + hofs;
    float* row = g_P + (size_t)h * SEQ * SEQ + (size_t)i * SEQ;
    const int n = i + 1;
    const int tid = threadIdx.x;
    const int lane = tid & 31, wid = tid >> 5;
    __shared__ float red[16];

    float m = -FLT_MAX;
    for (int j = tid; j < n; j += 256) m = fmaxf(m, row[j]);
#pragma unroll
    for (int o = 16; o; o >>= 1) m = fmaxf(m, __shfl_xor_sync(0xffffffffu, m, o));
    if (lane == 0) red[wid] = m;
    __syncthreads();
    m = red[0];
#pragma unroll
    for (int w = 1; w < 8; w++) m = fmaxf(m, red[w]);

    float s = 0.f;
    for (int j = tid; j < n; j += 256) s += expf(row[j] - m);
#pragma unroll
    for (int o = 16; o; o >>= 1) s += __shfl_xor_sync(0xffffffffu, s, o);
    if (lane == 0) red[8 + wid] = s;
    __syncthreads();
    float tot = 0.f;
#pragma unroll
    for (int w = 0; w < 8; w++) tot += red[8 + w];
    const float invs = 1.0f / tot;

    for (int j = tid; j < n; j += 256)
        row[j] = expf(row[j] - m) * invs;
}

// ======================= H2O sequential scan (per head-group) =======================
__global__ __launch_bounds__(128) void scan_kernel(int hofs)
{
    const int h = blockIdx.x + hofs;
    const int tid = threadIdx.x;
    const int lane = tid & 31, wid = tid >> 5;
    __shared__ float rowbuf[2][SEQ];
    __shared__ int   lst[128];
    __shared__ float skey[128];
    __shared__ unsigned mw[32];
    __shared__ unsigned skipm;
    const float* P = g_P + (size_t)h * SEQ * SEQ;
    unsigned* MB = g_M + h * SEQ * (SEQ / 32);

    // triangular acc0: P0[i,j] == 0 for i < j, so start at i = tid
    // (bit-identical: leading zero adds don't change the fp sum)
    if (tid < HB) {
        float s = 0.f;
        for (int i = tid; i < HB; i++) s += P[(size_t)i * SEQ + tid];
        skey[tid] = s;
        lst[tid] = tid;
    }
    {
        uint32_t dst = smem_u32(&rowbuf[HB & 1][0]);
        const float* src = P + (size_t)HB * SEQ;
        for (int g = tid; g < SEQ / 4; g += 128) cp16(dst + g * 16, src + g * 4);
        cp_commit();
    }
    cp_wait0();
    __syncthreads();

    int cnt = HB;
    for (int t = HB; t < SEQ; t++) {
        if (t + 1 < SEQ) {
            uint32_t dst = smem_u32(&rowbuf[(t + 1) & 1][0]);
            const float* src = P + (size_t)(t + 1) * SEQ;
            for (int g = tid; g < SEQ / 4; g += 128) cp16(dst + g * 16, src + g * 4);
            cp_commit();
        }
        if (wid == 0) {
            const float* Prow = rowbuf[t & 1];
            if (lane == 0) skipm = 0u;
            __syncwarp();

            const int r = cnt - (HB - 1);
            for (int rep = 0; rep < r; rep++) {
                const unsigned sk = skipm;
                float bv = FLT_MAX; int bidx = -1; int bpos = 0;
                for (int p = lane; p < cnt; p += 32) {
                    int ix = lst[p];
                    if (ix < 4 && ((sk >> ix) & 1u)) continue;
                    float v = skey[p];
                    if (v < bv || (v == bv && ix > bidx)) { bv = v; bidx = ix; bpos = p; }
                }
#pragma unroll
                for (int o = 16; o; o >>= 1) {
                    float ov = __shfl_down_sync(0xffffffffu, bv, o);
                    int   oi = __shfl_down_sync(0xffffffffu, bidx, o);
                    int   op = __shfl_down_sync(0xffffffffu, bpos, o);
                    if (ov < bv || (ov == bv && oi > bidx)) { bv = ov; bidx = oi; bpos = op; }
                }
                bidx = __shfl_sync(0xffffffffu, bidx, 0);
                bpos = __shfl_sync(0xffffffffu, bpos, 0);
                if (bidx >= 4) {
                    if (lane == 0) {
                        lst[bpos]  = lst[cnt - 1];
                        skey[bpos] = skey[cnt - 1];
                    }
                    cnt--;
                } else {
                    if (lane == 0) skipm |= (1u << bidx);
                }
                __syncwarp();
            }
            if (lane == 0) { lst[cnt] = t; skey[cnt] = 0.f; }
            cnt++;
            mw[lane] = 0u;
            __syncwarp();
            for (int p = lane; p < cnt; p += 32) {
                int ix = lst[p];
                skey[p] += Prow[ix];
                atomicOr(&mw[ix >> 5], 1u << (ix & 31));
            }
            __syncwarp();
            MB[t * 32 + lane] = mw[lane];
        }
        cp_wait0();
        __syncthreads();
    }
}

// ======================= masked renorm softmax + P@V (row-half) =======================
__global__ __launch_bounds__(128) void pv_kernel(int bofs)
{
    const int h = blockIdx.y;
    const int tid = threadIdx.x;
    const int lane = tid & 31, wid = tid >> 5;
    __shared__ float pv[224];
    __shared__ int   pj[224];
    __shared__ int   wbase[4];
    __shared__ float wsum[4];
    __shared__ int   s_cnt;
    __shared__ float s_sum;

    for (int u8 = 0; u8 < 8; u8++) {
        const int s = (blockIdx.x + bofs) * 8 + u8;
        const float* Prow = g_P + (size_t)h * SEQ * SEQ + (size_t)s * SEQ;
        const unsigned* mb = g_M + (h * SEQ + s) * (SEQ / 32);

        float pr[8]; bool al[8];
        int c = 0; float lsum = 0.f;
        const int j0 = tid * 8;
#pragma unroll
        for (int u = 0; u < 8; u++) {
            const int j = j0 + u;
            bool a;
            if (s < HB) a = (j <= s);
            else        a = (j <= s) && ((j + RB >= s) || ((mb[j >> 5] >> (j & 31)) & 1u));
            float val = a ? Prow[j] : 0.f;
            al[u] = a; pr[u] = val;
            if (a) { c++; lsum += val; }
        }
        int inc = c;
#pragma unroll
        for (int o = 1; o < 32; o <<= 1) {
            int v = __shfl_up_sync(0xffffffffu, inc, o);
            if (lane >= o) inc += v;
        }
        float ws = lsum;
#pragma unroll
        for (int o = 16; o; o >>= 1) ws += __shfl_xor_sync(0xffffffffu, ws, o);
        if (lane == 31) wbase[wid] = inc;
        if (lane == 0)  wsum[wid] = ws;
        __syncthreads();
        if (tid == 0) {
            int tot = 0;
#pragma unroll
            for (int w = 0; w < 4; w++) { int b = wbase[w]; wbase[w] = tot; tot += b; }
            s_cnt = tot;
            s_sum = wsum[0] + wsum[1] + wsum[2] + wsum[3];
        }
        __syncthreads();
        int k = wbase[wid] + inc - c;
#pragma unroll
        for (int u = 0; u < 8; u++)
            if (al[u]) { pv[k] = pr[u]; pj[k] = j0 + u; k++; }
        __syncthreads();

        const int cnt = s_cnt;
        const float inv = 1.0f / s_sum;
        const float* Vh = g_V + h * HD + tid;
        float acc = 0.f;
        int m2 = 0;
        for (; m2 + 4 <= cnt; m2 += 4) {
            acc += pv[m2 + 0] * Vh[(size_t)pj[m2 + 0] * DMODEL];
            acc += pv[m2 + 1] * Vh[(size_t)pj[m2 + 1] * DMODEL];
            acc += pv[m2 + 2] * Vh[(size_t)pj[m2 + 2] * DMODEL];
            acc += pv[m2 + 3] * Vh[(size_t)pj[m2 + 3] * DMODEL];
        }
        for (; m2 < cnt; m2++) acc += pv[m2] * Vh[(size_t)pj[m2] * DMODEL];

        float v = acc * inv;
        __half hv = __float2half(v);
        size_t oi = (size_t)s * DMODEL + h * HD + tid;
        g_AOhi[oi] = hv;
        g_AOlo[oi] = __float2half(v - __half2float(hv));
        __syncthreads();
    }
}

// ======================= launch (deep fork-join inside capture) =======================
extern "C" void kernel_launch(void* const* d_in, const int* in_sizes, int n_in,
                              void* d_out, int out_size)
{
    const float* X  = (const float*)d_in[0];
    const float* Wq = (const float*)d_in[2];
    const float* Wk = (const float*)d_in[3];
    const float* Wv = (const float*)d_in[4];
    const float* Wo = (const float*)d_in[5];
    float* out = (float*)d_out;

    static cudaStream_t s_aux = 0, s2 = 0;
    static cudaEvent_t ev_begin = 0, ev_xcvt = 0, ev_vdone = 0,
                       ev_rope = 0, ev_g0 = 0, ev_g1 = 0, ev_pvb = 0;
    if (!s_aux) {
        int lo_p, hi_p;
        cudaDeviceGetStreamPriorityRange(&lo_p, &hi_p);
        cudaStreamCreateWithPriority(&s_aux, cudaStreamNonBlocking, lo_p);
        cudaStreamCreateWithFlags(&s2, cudaStreamNonBlocking);
        cudaEventCreateWithFlags(&ev_begin, cudaEventDisableTiming);
        cudaEventCreateWithFlags(&ev_xcvt,  cudaEventDisableTiming);
        cudaEventCreateWithFlags(&ev_vdone, cudaEventDisableTiming);
        cudaEventCreateWithFlags(&ev_rope,  cudaEventDisableTiming);
        cudaEventCreateWithFlags(&ev_g0,    cudaEventDisableTiming);
        cudaEventCreateWithFlags(&ev_g1,    cudaEventDisableTiming);
        cudaEventCreateWithFlags(&ev_pvb,   cudaEventDisableTiming);
    }

    cudaFuncSetAttribute(mm_qkproj_kernel, cudaFuncAttributeMaxDynamicSharedMemorySize, MM_SMEM);
    cudaFuncSetAttribute(mm_v_kernel,      cudaFuncAttributeMaxDynamicSharedMemorySize, MM_SMEM);
    cudaFuncSetAttribute(mm_qk_kernel,     cudaFuncAttributeMaxDynamicSharedMemorySize, MM_SMEM);
    cudaFuncSetAttribute(mm_o_kernel,      cudaFuncAttributeMaxDynamicSharedMemorySize, MM_SMEM);

    // fork
    cudaEventRecord(ev_begin, 0);
    cudaStreamWaitEvent(s_aux, ev_begin, 0);
    cudaStreamWaitEvent(s2, ev_begin, 0);

    // aux: deferred weight conversions + V projection
    cvt_aux_kernel<<<(2 * W4 + 255) / 256, 256, 0, s_aux>>>(Wv, Wo);

    // main: X/Wq/Wk conversion, Q/K projections, rope
    cvt_main_kernel<<<(X4 + 2 * W4 + 255) / 256, 256>>>(X, Wq, Wk);
    cudaEventRecord(ev_xcvt, 0);

    mm_qkproj_kernel<<<dim3(DMODEL / 64, SEQ / 128, 2), 256, MM_SMEM>>>();
    rope_kernel<<<dim3((SEQ * NH * 64) / 256, 2), 256>>>();
    cudaEventRecord(ev_rope, 0);

    // aux: V projection once X is converted
    cudaStreamWaitEvent(s_aux, ev_xcvt, 0);
    mm_v_kernel<<<dim3(DMODEL / 64, SEQ / 128), 256, MM_SMEM, s_aux>>>();
    cudaEventRecord(ev_vdone, s_aux);

    // head-group 0 on default: qk -> softmax -> scan
    mm_qk_kernel<<<dim3(SEQ / 64, SEQ / 128, NH / 2), 256, MM_SMEM>>>(0);
    softmax_kernel<<<dim3(SEQ, NH / 2), 256>>>(0);
    scan_kernel<<<NH / 2, 128>>>(0);
    cudaEventRecord(ev_g0, 0);

    // head-group 1 on s2
    cudaStreamWaitEvent(s2, ev_rope, 0);
    mm_qk_kernel<<<dim3(SEQ / 64, SEQ / 128, NH / 2), 256, MM_SMEM, s2>>>(NH / 2);
    softmax_kernel<<<dim3(SEQ, NH / 2), 256, 0, s2>>>(NH / 2);
    scan_kernel<<<NH / 2, 128, 0, s2>>>(NH / 2);
    cudaEventRecord(ev_g1, s2);

    // pv halves
    cudaStreamWaitEvent(0, ev_g1, 0);
    cudaStreamWaitEvent(0, ev_vdone, 0);
    cudaStreamWaitEvent(s2, ev_g0, 0);
    cudaStreamWaitEvent(s2, ev_vdone, 0);

    pv_kernel<<<dim3(SEQ / 16, NH), 128>>>(0);
    pv_kernel<<<dim3(SEQ / 16, NH), 128, 0, s2>>>(SEQ / 16);
    cudaEventRecord(ev_pvb, s2);

    // mm_o halves: first half overlaps second pv half
    mm_o_kernel<<<dim3(DMODEL / 64, SEQ / 256), 256, MM_SMEM>>>(out, 0);
    cudaStreamWaitEvent(0, ev_pvb, 0);
    mm_o_kernel<<<dim3(DMODEL / 64, SEQ / 256), 256, MM_SMEM>>>(out, SEQ / 256);
}